// round 7
// baseline (speedup 1.0000x reference)
#include <cuda_runtime.h>
#include <math.h>
#include <stdint.h>

// Shapes (fixed)
#define NVOX 40000
#define PPTS 32
#define CIN  10
#define GCH  64
#define HID  128
#define H3   384
#define MB   64
#define NTH  512
#define NBLOCKS (NVOX / MB)     // 625
#define KT   32                 // K rows per weight tile
#define STR  320                // sA row: [x(64) | h1(128) | h2(128)]

// Stacked transposed weights WT[k][gate_col]:
// rows [0,64) Wih0^T, [64,192) Whh0^T, [192,320) Wih1^T, [320,448) Whh1^T
#define WT_ROWS 448
__device__ float g_WT[WT_ROWS * H3];
__device__ int   g_perm[NVOX];
__device__ int   g_hist[32];
__device__ int   g_off[33];
__device__ int   g_cursor[32];

__global__ void prep_weights(const float* __restrict__ wih0, const float* __restrict__ whh0,
                             const float* __restrict__ wih1, const float* __restrict__ whh1) {
    int idx = blockIdx.x * blockDim.x + threadIdx.x;
    const int total = WT_ROWS * H3;
    for (; idx < total; idx += gridDim.x * blockDim.x) {
        int row = idx / H3;
        int j   = idx - row * H3;
        float v;
        if (row < 64)       v = wih0[j * 64  + row];
        else if (row < 192) v = whh0[j * 128 + (row - 64)];
        else if (row < 320) v = wih1[j * 128 + (row - 192)];
        else                v = whh1[j * 128 + (row - 320)];
        g_WT[idx] = v;
    }
}

// ---- length binning (order within a bin unimportant: per-voxel outputs independent) ----
__global__ void zero_hist() {
    if (threadIdx.x < 32) { g_hist[threadIdx.x] = 0; g_cursor[threadIdx.x] = 0; }
}
__global__ void hist_kernel(const int* __restrict__ vnp) {
    int i = blockIdx.x * blockDim.x + threadIdx.x;
    for (; i < NVOX; i += gridDim.x * blockDim.x)
        atomicAdd(&g_hist[vnp[i] - 1], 1);
}
__global__ void scan_kernel() {
    if (threadIdx.x == 0) {
        int acc = 0; g_off[0] = 0;
        for (int b = 0; b < 32; ++b) { acc += g_hist[b]; g_off[b + 1] = acc; }
    }
}
__global__ void sortblocks(const int* __restrict__ vnp) {
    __shared__ int cnt[32];
    __shared__ int sbase[32];
    const int tid = threadIdx.x;
    if (tid < 32) cnt[tid] = 0;
    __syncthreads();
    int i = blockIdx.x * 256 + tid;
    int len = -1, myrank = 0;
    if (i < NVOX) { len = vnp[i] - 1; myrank = atomicAdd(&cnt[len], 1); }
    __syncthreads();
    if (tid < 32 && cnt[tid] > 0) sbase[tid] = atomicAdd(&g_cursor[tid], cnt[tid]);
    __syncthreads();
    if (i < NVOX) g_perm[g_off[len] + sbase[len] + myrank] = i;
}

// ---- f32x2 helpers ----
__device__ __forceinline__ unsigned long long pack2(float lo, float hi) {
    unsigned long long r;
    asm("mov.b64 %0, {%1, %2};" : "=l"(r) : "f"(lo), "f"(hi));
    return r;
}
__device__ __forceinline__ void unpack2(unsigned long long v, float& lo, float& hi) {
    asm("mov.b64 {%0, %1}, %2;" : "=f"(lo), "=f"(hi) : "l"(v));
}
__device__ __forceinline__ void ffma2(unsigned long long& d, unsigned long long a, unsigned long long b) {
    asm("fma.rn.f32x2 %0, %1, %2, %0;" : "+l"(d) : "l"(a), "l"(b));
}
// Fast gates via MUFU paths (~2 ulp): saturate correctly at both tails.
__device__ __forceinline__ float fsig(float x)  { return __fdividef(1.f, 1.f + __expf(-x)); }
__device__ __forceinline__ float ftanh_(float x){ return 1.f - __fdividef(2.f, __expf(2.f * x) + 1.f); }

// cp.async one KT x 384 weight tile (49152 B = 3072 x 16B, 6 per thread at 512 thr)
__device__ __forceinline__ void cp_tile(uint32_t dst_s, const float* __restrict__ src, int tid) {
    const char* s = (const char*)src;
    #pragma unroll
    for (int r = 0; r < 6; ++r) {
        int idx = tid + r * NTH;
        asm volatile("cp.async.cg.shared.global [%0], [%1], 16;\n"
                     :: "r"(dst_s + idx * 16), "l"(s + (size_t)idx * 16) : "memory");
    }
    asm volatile("cp.async.commit_group;\n" ::: "memory");
}

// One KT-tile GEMM: thread (tx,wy) -> voxels wy*4..wy*4+3, per-gate cols 4tx..4tx+3.
__device__ __forceinline__ void tile_compute(
    const float* __restrict__ buf, const float* __restrict__ sA0, int tx, int wy,
    unsigned long long (&aR)[4][2], unsigned long long (&aZ)[4][2], unsigned long long (&aN)[4][2])
{
    const float* wcol = buf + 4 * tx;
    #pragma unroll 2
    for (int kk4 = 0; kk4 < KT / 4; ++kk4) {
        float4 a4[4];
        #pragma unroll
        for (int i = 0; i < 4; ++i)
            a4[i] = *(const float4*)(sA0 + (wy * 4 + i) * STR + kk4 * 4);
        #pragma unroll
        for (int j = 0; j < 4; ++j) {
            const float* wrow = wcol + (kk4 * 4 + j) * H3;
            ulonglong2 wr = *(const ulonglong2*)(wrow);
            ulonglong2 wz = *(const ulonglong2*)(wrow + HID);
            ulonglong2 wn = *(const ulonglong2*)(wrow + 2 * HID);
            #pragma unroll
            for (int i = 0; i < 4; ++i) {
                float a = (j == 0) ? a4[i].x : (j == 1) ? a4[i].y
                        : (j == 2) ? a4[i].z : a4[i].w;
                unsigned long long a2 = pack2(a, a);
                ffma2(aR[i][0], a2, wr.x); ffma2(aR[i][1], a2, wr.y);
                ffma2(aZ[i][0], a2, wz.x); ffma2(aZ[i][1], a2, wz.y);
                ffma2(aN[i][0], a2, wn.x); ffma2(aN[i][1], a2, wn.y);
            }
        }
    }
}

// Double-buffered GEMM segment; prefetch chains into the NEXT segment/step via nextRowAfter.
template<int SEGK>
__device__ __forceinline__ void gemm_seg(
    int rowBase, int nextRowAfter, const float* __restrict__ sA0,
    const float* sWb[2], const uint32_t sWa[2], int& pbuf,
    int tid, int tx, int wy,
    unsigned long long (&aR)[4][2], unsigned long long (&aZ)[4][2], unsigned long long (&aN)[4][2])
{
    const int NT = SEGK / KT;
    #pragma unroll 1
    for (int tile = 0; tile < NT; ++tile) {
        asm volatile("cp.async.wait_group 0;\n" ::: "memory");
        __syncthreads();
        int nrow = (tile + 1 < NT) ? rowBase + (tile + 1) * KT : nextRowAfter;
        cp_tile(sWa[pbuf ^ 1], g_WT + (size_t)nrow * H3, tid);
        tile_compute(sWb[pbuf], sA0 + tile * KT, tx, wy, aR, aZ, aN);
        pbuf ^= 1;
    }
}

__global__ void __launch_bounds__(NTH)
pfn_kernel(const float* __restrict__ inputs, const int* __restrict__ vnp,
           const float* __restrict__ conv_w,
           const float* __restrict__ bn_gamma, const float* __restrict__ bn_beta,
           const float* __restrict__ bn_mean,  const float* __restrict__ bn_var,
           const float* __restrict__ b_ih0, const float* __restrict__ b_hh0,
           const float* __restrict__ b_ih1, const float* __restrict__ b_hh1,
           float* __restrict__ out)
{
    extern __shared__ float sm[];
    float* sW0  = sm;                     // 12288
    float* sW1  = sW0 + KT * H3;          // 12288
    float* sA   = sW1 + KT * H3;          // 64*320
    float* sCw  = sA  + MB * STR;         // 640
    float* sCb  = sCw + GCH * CIN;        // 64
    // combined bias blocks per layer: [0,128)=bir+bhr [128,256)=biz+bhz [256,384)=bin [384,512)=bhn
    float* sBc0 = sCb  + GCH;             // 512
    float* sBc1 = sBc0 + 512;             // 512
    int*   sLen = (int*)(sBc1 + 512);     // 64
    int*   sVox = sLen + MB;              // 64

    const int tid = threadIdx.x;
    const int tx = tid & 31, wy = tid >> 5;       // 16 warps; warp wy owns voxels wy*4..+3
    const int cv = tid >> 3, cg = (tid & 7) * 8;  // conv: 1 voxel, 8 cols per thread (same warp!)
    const int pbase = (NBLOCKS - 1 - (int)blockIdx.x) * MB;   // LPT: longest first

    const float* sWb[2] = { sW0, sW1 };
    uint32_t sWa[2] = { (uint32_t)__cvta_generic_to_shared(sW0),
                        (uint32_t)__cvta_generic_to_shared(sW1) };

    // ---- one-time setup ----
    for (int idx = tid; idx < MB * STR; idx += NTH) sA[idx] = 0.f;
    for (int idx = tid; idx < GCH * CIN; idx += NTH) {
        int g = idx / CIN;
        float sc = bn_gamma[g] * rsqrtf(bn_var[g] + 1e-5f);
        sCw[idx] = conv_w[idx] * sc;
    }
    for (int idx = tid; idx < GCH; idx += NTH) {
        float sc = bn_gamma[idx] * rsqrtf(bn_var[idx] + 1e-5f);
        sCb[idx] = bn_beta[idx] - bn_mean[idx] * sc;
    }
    for (int idx = tid; idx < 512; idx += NTH) {
        float v0, v1;
        if (idx < 256)      { v0 = b_ih0[idx] + b_hh0[idx]; v1 = b_ih1[idx] + b_hh1[idx]; }
        else if (idx < 384) { v0 = b_ih0[idx]; v1 = b_ih1[idx]; }          // xn bias
        else                { v0 = b_hh0[idx - 128]; v1 = b_hh1[idx - 128]; } // hn bias
        sBc0[idx] = v0; sBc1[idx] = v1;
    }
    for (int idx = tid; idx < MB; idx += NTH) {
        int vox = g_perm[pbase + idx];
        sVox[idx] = vox;
        sLen[idx] = vnp[vox];
    }
    __syncthreads();

    int tmax = 0;
    for (int v = 0; v < MB; ++v) tmax = max(tmax, sLen[v]);
    const size_t inbase = (size_t)sVox[cv] * PPTS;

    float mx[8];
    #pragma unroll
    for (int c = 0; c < 8; ++c) mx[c] = 0.f;

    unsigned long long aR[4][2], aZ[4][2], aXN[4][2], aHN[4][2];
    int pbuf = 0;
    cp_tile(sWa[0], g_WT, tid);   // prime the pipeline with tile row 0

    for (int t = 0; t < tmax; ++t) {
        // ---- conv (warp-private: cv belongs to this warp's voxel set) ----
        {
            const float2* ip = (const float2*)(inputs + (inbase + t) * CIN);
            float2 i0 = ip[0], i1 = ip[1], i2 = ip[2], i3 = ip[3], i4 = ip[4];
            float in[10] = { i0.x, i0.y, i1.x, i1.y, i2.x, i2.y, i3.x, i3.y, i4.x, i4.y };
            float xv[8];
            #pragma unroll
            for (int c8 = 0; c8 < 8; ++c8) {
                int g = cg + c8;
                float s = sCb[g];
                const float* pw = sCw + g * CIN;
                #pragma unroll
                for (int c = 0; c < CIN; ++c) s = fmaf(in[c], pw[c], s);
                s = fmaxf(s, 0.f);
                xv[c8] = s;
                mx[c8] = fmaxf(mx[c8], s);
            }
            *(float4*)(sA + cv * STR + cg)     = make_float4(xv[0], xv[1], xv[2], xv[3]);
            *(float4*)(sA + cv * STR + cg + 4) = make_float4(xv[4], xv[5], xv[6], xv[7]);
        }
        // x is warp-private; first tile's syncthreads orders only the shared weight buffer.

        // ======== layer 0 ========
        {
            int gc = 4 * tx;
            #pragma unroll
            for (int p = 0; p < 2; ++p) {
                unsigned long long br  = pack2(sBc0[gc + 2*p],       sBc0[gc + 2*p + 1]);
                unsigned long long bz  = pack2(sBc0[128 + gc + 2*p], sBc0[128 + gc + 2*p + 1]);
                unsigned long long bxn = pack2(sBc0[256 + gc + 2*p], sBc0[256 + gc + 2*p + 1]);
                unsigned long long bhn = pack2(sBc0[384 + gc + 2*p], sBc0[384 + gc + 2*p + 1]);
                #pragma unroll
                for (int i = 0; i < 4; ++i) { aR[i][p] = br; aZ[i][p] = bz; aXN[i][p] = bxn; aHN[i][p] = bhn; }
            }
        }
        gemm_seg<GCH>(0,  64,  sA + 0,  sWb, sWa, pbuf, tid, tx, wy, aR, aZ, aXN);
        gemm_seg<HID>(64, 192, sA + 64, sWb, sWa, pbuf, tid, tx, wy, aR, aZ, aHN);
        #pragma unroll
        for (int i = 0; i < 4; ++i) {
            int v = wy * 4 + i;
            float4 hp = *(const float4*)(sA + v * STR + 64 + 4 * tx);
            float rr[4], zz[4], xn[4], hn[4];
            unpack2(aR[i][0],  rr[0], rr[1]); unpack2(aR[i][1],  rr[2], rr[3]);
            unpack2(aZ[i][0],  zz[0], zz[1]); unpack2(aZ[i][1],  zz[2], zz[3]);
            unpack2(aXN[i][0], xn[0], xn[1]); unpack2(aXN[i][1], xn[2], xn[3]);
            unpack2(aHN[i][0], hn[0], hn[1]); unpack2(aHN[i][1], hn[2], hn[3]);
            float hv[4] = {hp.x, hp.y, hp.z, hp.w};
            #pragma unroll
            for (int j = 0; j < 4; ++j) {
                float r = fsig(rr[j]);
                float z = fsig(zz[j]);
                float n = ftanh_(fmaf(r, hn[j], xn[j]));
                hv[j] = (1.f - z) * n + z * hv[j];
            }
            // h1 rows are warp-private: no barrier needed around this write
            *(float4*)(sA + v * STR + 64 + 4 * tx) = make_float4(hv[0], hv[1], hv[2], hv[3]);
        }

        // ======== layer 1 ========
        {
            int gc = 4 * tx;
            #pragma unroll
            for (int p = 0; p < 2; ++p) {
                unsigned long long br  = pack2(sBc1[gc + 2*p],       sBc1[gc + 2*p + 1]);
                unsigned long long bz  = pack2(sBc1[128 + gc + 2*p], sBc1[128 + gc + 2*p + 1]);
                unsigned long long bxn = pack2(sBc1[256 + gc + 2*p], sBc1[256 + gc + 2*p + 1]);
                unsigned long long bhn = pack2(sBc1[384 + gc + 2*p], sBc1[384 + gc + 2*p + 1]);
                #pragma unroll
                for (int i = 0; i < 4; ++i) { aR[i][p] = br; aZ[i][p] = bz; aXN[i][p] = bxn; aHN[i][p] = bhn; }
            }
        }
        gemm_seg<HID>(192, 320, sA + 64,  sWb, sWa, pbuf, tid, tx, wy, aR, aZ, aXN);
        gemm_seg<HID>(320, 0,   sA + 192, sWb, sWa, pbuf, tid, tx, wy, aR, aZ, aHN); // chain to next step
        #pragma unroll
        for (int i = 0; i < 4; ++i) {
            int v = wy * 4 + i;
            float4 hp = *(const float4*)(sA + v * STR + 192 + 4 * tx);
            float rr[4], zz[4], xn[4], hn[4];
            unpack2(aR[i][0],  rr[0], rr[1]); unpack2(aR[i][1],  rr[2], rr[3]);
            unpack2(aZ[i][0],  zz[0], zz[1]); unpack2(aZ[i][1],  zz[2], zz[3]);
            unpack2(aXN[i][0], xn[0], xn[1]); unpack2(aXN[i][1], xn[2], xn[3]);
            unpack2(aHN[i][0], hn[0], hn[1]); unpack2(aHN[i][1], hn[2], hn[3]);
            float hv[4] = {hp.x, hp.y, hp.z, hp.w};
            #pragma unroll
            for (int j = 0; j < 4; ++j) {
                float r = fsig(rr[j]);
                float z = fsig(zz[j]);
                float n = ftanh_(fmaf(r, hn[j], xn[j]));
                hv[j] = (1.f - z) * n + z * hv[j];
            }
            float4 h4 = make_float4(hv[0], hv[1], hv[2], hv[3]);
            *(float4*)(sA + v * STR + 192 + 4 * tx) = h4;   // warp-private
            if (t == sLen[v] - 1)
                *(float4*)(out + (size_t)sVox[v] * (GCH + HID) + GCH + 4 * tx) = h4;
        }
    }

    // ---- tail: conv+max only (register-resident, no barriers needed) ----
    for (int t = tmax; t < PPTS; ++t) {
        const float2* ip = (const float2*)(inputs + (inbase + t) * CIN);
        float2 i0 = ip[0], i1 = ip[1], i2 = ip[2], i3 = ip[3], i4 = ip[4];
        float in[10] = { i0.x, i0.y, i1.x, i1.y, i2.x, i2.y, i3.x, i3.y, i4.x, i4.y };
        #pragma unroll
        for (int c8 = 0; c8 < 8; ++c8) {
            int g = cg + c8;
            float s = sCb[g];
            const float* pw = sCw + g * CIN;
            #pragma unroll
            for (int c = 0; c < CIN; ++c) s = fmaf(in[c], pw[c], s);
            mx[c8] = fmaxf(mx[c8], fmaxf(s, 0.f));
        }
    }

    // max-features output (thread owns voxel cv, cols cg..cg+7)
    float* po = out + (size_t)sVox[cv] * (GCH + HID) + cg;
    *(float4*)(po)     = make_float4(mx[0], mx[1], mx[2], mx[3]);
    *(float4*)(po + 4) = make_float4(mx[4], mx[5], mx[6], mx[7]);
}

extern "C" void kernel_launch(void* const* d_in, const int* in_sizes, int n_in,
                              void* d_out, int out_size) {
    const float* inputs = (const float*)d_in[0];
    const int*   vnp    = (const int*)  d_in[1];
    // d_in[2] = mask (unused)
    const float* conv_w = (const float*)d_in[3];
    const float* bn_g   = (const float*)d_in[4];
    const float* bn_b   = (const float*)d_in[5];
    const float* bn_m   = (const float*)d_in[6];
    const float* bn_v   = (const float*)d_in[7];
    const float* wih0   = (const float*)d_in[8];
    const float* whh0   = (const float*)d_in[9];
    const float* bih0   = (const float*)d_in[10];
    const float* bhh0   = (const float*)d_in[11];
    const float* wih1   = (const float*)d_in[12];
    const float* whh1   = (const float*)d_in[13];
    const float* bih1   = (const float*)d_in[14];
    const float* bhh1   = (const float*)d_in[15];
    float* out = (float*)d_out;

    const int smem_bytes = (2 * KT * H3 + MB * STR + GCH * CIN + GCH + 1024) * (int)sizeof(float)
                           + 2 * MB * (int)sizeof(int);
    cudaFuncSetAttribute(pfn_kernel, cudaFuncAttributeMaxDynamicSharedMemorySize, smem_bytes);

    zero_hist<<<1, 32>>>();
    hist_kernel<<<160, 256>>>(vnp);
    scan_kernel<<<1, 32>>>();
    sortblocks<<<(NVOX + 255) / 256, 256>>>(vnp);
    prep_weights<<<336, 512>>>(wih0, whh0, wih1, whh1);
    pfn_kernel<<<NBLOCKS, NTH, smem_bytes>>>(inputs, vnp, conv_w, bn_g, bn_b, bn_m, bn_v,
                                             bih0, bhh0, bih1, bhh1, out);
}

// round 8
// speedup vs baseline: 1.0291x; 1.0291x over previous
#include <cuda_runtime.h>
#include <math.h>
#include <stdint.h>

// Shapes (fixed)
#define NVOX 40000
#define PPTS 32
#define CIN  10
#define GCH  64
#define HID  128
#define H3   384
#define MB   64
#define NTH  256
#define NBLOCKS (NVOX / MB)     // 625
#define KT   32                 // K rows per weight tile
#define STR  320                // sA row: [x(64) | h1(128) | h2(128)]

// Stacked transposed weights WT[k][gate_col]:
// rows [0,64) Wih0^T, [64,192) Whh0^T, [192,320) Wih1^T, [320,448) Whh1^T
#define WT_ROWS 448
__device__ float g_WT[WT_ROWS * H3];
__device__ int   g_perm[NVOX];
__device__ int   g_hist[32];
__device__ int   g_off[33];
__device__ int   g_cursor[32];

__global__ void prep_weights(const float* __restrict__ wih0, const float* __restrict__ whh0,
                             const float* __restrict__ wih1, const float* __restrict__ whh1) {
    int idx = blockIdx.x * blockDim.x + threadIdx.x;
    const int total = WT_ROWS * H3;
    for (; idx < total; idx += gridDim.x * blockDim.x) {
        int row = idx / H3;
        int j   = idx - row * H3;
        float v;
        if (row < 64)       v = wih0[j * 64  + row];
        else if (row < 192) v = whh0[j * 128 + (row - 64)];
        else if (row < 320) v = wih1[j * 128 + (row - 192)];
        else                v = whh1[j * 128 + (row - 320)];
        g_WT[idx] = v;
    }
}

// ---- length binning (order within a bin unimportant: per-voxel outputs independent) ----
__global__ void zero_hist() {
    if (threadIdx.x < 32) { g_hist[threadIdx.x] = 0; g_cursor[threadIdx.x] = 0; }
}
__global__ void hist_kernel(const int* __restrict__ vnp) {
    int i = blockIdx.x * blockDim.x + threadIdx.x;
    for (; i < NVOX; i += gridDim.x * blockDim.x)
        atomicAdd(&g_hist[vnp[i] - 1], 1);
}
__global__ void scan_kernel() {
    if (threadIdx.x == 0) {
        int acc = 0; g_off[0] = 0;
        for (int b = 0; b < 32; ++b) { acc += g_hist[b]; g_off[b + 1] = acc; }
    }
}
__global__ void sortblocks(const int* __restrict__ vnp) {
    __shared__ int cnt[32];
    __shared__ int sbase[32];
    const int tid = threadIdx.x;
    if (tid < 32) cnt[tid] = 0;
    __syncthreads();
    int i = blockIdx.x * 256 + tid;
    int len = -1, myrank = 0;
    if (i < NVOX) { len = vnp[i] - 1; myrank = atomicAdd(&cnt[len], 1); }
    __syncthreads();
    if (tid < 32 && cnt[tid] > 0) sbase[tid] = atomicAdd(&g_cursor[tid], cnt[tid]);
    __syncthreads();
    if (i < NVOX) g_perm[g_off[len] + sbase[len] + myrank] = i;
}

// ---- f32x2 helpers ----
__device__ __forceinline__ unsigned long long pack2(float lo, float hi) {
    unsigned long long r;
    asm("mov.b64 %0, {%1, %2};" : "=l"(r) : "f"(lo), "f"(hi));
    return r;
}
__device__ __forceinline__ void unpack2(unsigned long long v, float& lo, float& hi) {
    asm("mov.b64 {%0, %1}, %2;" : "=f"(lo), "=f"(hi) : "l"(v));
}
__device__ __forceinline__ void ffma2(unsigned long long& d, unsigned long long a, unsigned long long b) {
    asm("fma.rn.f32x2 %0, %1, %2, %0;" : "+l"(d) : "l"(a), "l"(b));
}
// Fast gates via MUFU paths (~2 ulp): saturate correctly at both tails.
__device__ __forceinline__ float fsig(float x)  { return __fdividef(1.f, 1.f + __expf(-x)); }
__device__ __forceinline__ float ftanh_(float x){ return 1.f - __fdividef(2.f, __expf(2.f * x) + 1.f); }

// cp.async one KT x 384 weight tile (49152 B = 3072 x 16B, 12 per thread at 256 thr)
__device__ __forceinline__ void cp_tile(uint32_t dst_s, const float* __restrict__ src, int tid) {
    const char* s = (const char*)src;
    #pragma unroll
    for (int r = 0; r < 12; ++r) {
        int idx = tid + r * NTH;
        asm volatile("cp.async.cg.shared.global [%0], [%1], 16;\n"
                     :: "r"(dst_s + idx * 16), "l"(s + (size_t)idx * 16) : "memory");
    }
    asm volatile("cp.async.commit_group;\n" ::: "memory");
}

// One KT-tile GEMM: thread (tx,ty) -> voxels ty*8..ty*8+7, per-gate cols 4tx..4tx+3.
// Software-pipelined: weight row kk+1 prefetched during kk's FFMA2 block.
// (kk=31 prefetch over-reads one row into the adjacent smem region: allocated, unused.)
__device__ __forceinline__ void tile_compute(
    const float* __restrict__ buf, const float* __restrict__ sA0, int tx, int ty,
    unsigned long long (&aR)[8][2], unsigned long long (&aZ)[8][2], unsigned long long (&aN)[8][2])
{
    const float* wcol = buf + 4 * tx;
    ulonglong2 wr = *(const ulonglong2*)(wcol);
    ulonglong2 wz = *(const ulonglong2*)(wcol + HID);
    ulonglong2 wn = *(const ulonglong2*)(wcol + 2 * HID);
    #pragma unroll 2
    for (int kk4 = 0; kk4 < KT / 4; ++kk4) {
        float4 a4[8];
        #pragma unroll
        for (int i = 0; i < 8; ++i)
            a4[i] = *(const float4*)(sA0 + (ty * 8 + i) * STR + kk4 * 4);
        #pragma unroll
        for (int j = 0; j < 4; ++j) {
            const float* nrow = wcol + (kk4 * 4 + j + 1) * H3;
            ulonglong2 nr = *(const ulonglong2*)(nrow);
            ulonglong2 nz = *(const ulonglong2*)(nrow + HID);
            ulonglong2 nn = *(const ulonglong2*)(nrow + 2 * HID);
            #pragma unroll
            for (int i = 0; i < 8; ++i) {
                float a = (j == 0) ? a4[i].x : (j == 1) ? a4[i].y
                        : (j == 2) ? a4[i].z : a4[i].w;
                unsigned long long a2 = pack2(a, a);
                ffma2(aR[i][0], a2, wr.x); ffma2(aR[i][1], a2, wr.y);
                ffma2(aZ[i][0], a2, wz.x); ffma2(aZ[i][1], a2, wz.y);
                ffma2(aN[i][0], a2, wn.x); ffma2(aN[i][1], a2, wn.y);
            }
            wr = nr; wz = nz; wn = nn;
        }
    }
}

// Chained double-buffered GEMM segment over WT rows [rowBase, rowBase+SEGK).
// On entry: one cp group outstanding, targeting buffer pbuf, holding row rowBase.
// Each tile waits, syncs, issues the next row in the global chain (wrapping into
// nextRowAfter at segment end), computes, flips pbuf.
template<int SEGK>
__device__ __forceinline__ void gemm_seg(
    int rowBase, int nextRowAfter, const float* __restrict__ sA0,
    const float* const sWb[2], const uint32_t sWa[2], int& pbuf,
    int tid, int tx, int ty,
    unsigned long long (&aR)[8][2], unsigned long long (&aZ)[8][2], unsigned long long (&aN)[8][2])
{
    const int NT = SEGK / KT;
    #pragma unroll 1
    for (int tile = 0; tile < NT; ++tile) {
        asm volatile("cp.async.wait_group 0;\n" ::: "memory");
        __syncthreads();
        int nrow = (tile + 1 < NT) ? rowBase + (tile + 1) * KT : nextRowAfter;
        cp_tile(sWa[pbuf ^ 1], g_WT + (size_t)nrow * H3, tid);
        tile_compute(sWb[pbuf], sA0 + tile * KT, tx, ty, aR, aZ, aN);
        pbuf ^= 1;
    }
}

__global__ void __launch_bounds__(NTH)
pfn_kernel(const float* __restrict__ inputs, const int* __restrict__ vnp,
           const float* __restrict__ conv_w,
           const float* __restrict__ bn_gamma, const float* __restrict__ bn_beta,
           const float* __restrict__ bn_mean,  const float* __restrict__ bn_var,
           const float* __restrict__ b_ih0, const float* __restrict__ b_hh0,
           const float* __restrict__ b_ih1, const float* __restrict__ b_hh1,
           float* __restrict__ out)
{
    extern __shared__ float sm[];
    float* sW0  = sm;                     // 12288
    float* sW1  = sW0 + KT * H3;          // 12288
    float* sA   = sW1 + KT * H3;          // 64*320
    float* sMax = sA  + MB * STR;         // 64*64
    float* sCw  = sMax + MB * GCH;        // 640
    float* sCb  = sCw + GCH * CIN;        // 64
    // combined bias per layer: [0,128)=bir+bhr [128,256)=biz+bhz [256,384)=bin [384,512)=bhn
    float* sBc0 = sCb  + GCH;             // 512
    float* sBc1 = sBc0 + 512;             // 512
    int*   sLen = (int*)(sBc1 + 512);     // 64
    int*   sVox = sLen + MB;              // 64

    const int tid = threadIdx.x;
    const int tx = tid & 31, ty = tid >> 5;        // warp ty owns voxels ty*8..ty*8+7
    const int cv = tid >> 2, cg = (tid & 3) * 16;  // conv: 1 voxel, 16 cols (same warp as GEMM owner)
    const int pbase = (NBLOCKS - 1 - (int)blockIdx.x) * MB;   // LPT: longest first

    const float* sWb[2] = { sW0, sW1 };
    uint32_t sWa[2] = { (uint32_t)__cvta_generic_to_shared(sW0),
                        (uint32_t)__cvta_generic_to_shared(sW1) };

    // ---- one-time setup ----
    for (int idx = tid; idx < MB * STR; idx += NTH) sA[idx] = 0.f;
    for (int idx = tid; idx < MB * GCH; idx += NTH) sMax[idx] = 0.f;
    for (int idx = tid; idx < GCH * CIN; idx += NTH) {
        int g = idx / CIN;
        float sc = bn_gamma[g] * rsqrtf(bn_var[g] + 1e-5f);
        sCw[idx] = conv_w[idx] * sc;
    }
    for (int idx = tid; idx < GCH; idx += NTH) {
        float sc = bn_gamma[idx] * rsqrtf(bn_var[idx] + 1e-5f);
        sCb[idx] = bn_beta[idx] - bn_mean[idx] * sc;
    }
    for (int idx = tid; idx < 512; idx += NTH) {
        float v0, v1;
        if (idx < 256)      { v0 = b_ih0[idx] + b_hh0[idx]; v1 = b_ih1[idx] + b_hh1[idx]; }
        else if (idx < 384) { v0 = b_ih0[idx]; v1 = b_ih1[idx]; }             // xn bias
        else                { v0 = b_hh0[idx - 128]; v1 = b_hh1[idx - 128]; } // hn bias
        sBc0[idx] = v0; sBc1[idx] = v1;
    }
    for (int idx = tid; idx < MB; idx += NTH) {
        int vox = g_perm[pbase + idx];
        sVox[idx] = vox;
        sLen[idx] = vnp[vox];
    }
    __syncthreads();

    int tmax = 0;
    for (int v = 0; v < MB; ++v) tmax = max(tmax, sLen[v]);
    const size_t inbase = (size_t)sVox[cv] * PPTS;

    unsigned long long aR[8][2], aZ[8][2], aXN[8][2], aHN[8][2];
    int pbuf = 0;
    cp_tile(sWa[0], g_WT, tid);   // prime the chain with row 0

    for (int t = 0; t < tmax; ++t) {
        // ---- conv+BN+ReLU (warp-private: cv in this warp's voxel set; 16 cols/thread) ----
        {
            const float2* ip = (const float2*)(inputs + (inbase + t) * CIN);
            float2 i0 = ip[0], i1 = ip[1], i2 = ip[2], i3 = ip[3], i4 = ip[4];
            float in[10] = { i0.x, i0.y, i1.x, i1.y, i2.x, i2.y, i3.x, i3.y, i4.x, i4.y };
            #pragma unroll
            for (int q = 0; q < 4; ++q) {
                float xv[4];
                #pragma unroll
                for (int c4 = 0; c4 < 4; ++c4) {
                    int g = cg + q * 4 + c4;
                    float s = sCb[g];
                    const float* pw = sCw + g * CIN;
                    #pragma unroll
                    for (int c = 0; c < CIN; ++c) s = fmaf(in[c], pw[c], s);
                    xv[c4] = fmaxf(s, 0.f);
                }
                float4 x4 = make_float4(xv[0], xv[1], xv[2], xv[3]);
                *(float4*)(sA + cv * STR + cg + q * 4) = x4;
                float4 m4 = *(float4*)(sMax + cv * GCH + cg + q * 4);   // same-thread RMW: no race
                m4.x = fmaxf(m4.x, x4.x); m4.y = fmaxf(m4.y, x4.y);
                m4.z = fmaxf(m4.z, x4.z); m4.w = fmaxf(m4.w, x4.w);
                *(float4*)(sMax + cv * GCH + cg + q * 4) = m4;
            }
        }
        // x / h1 / h2 rows are warp-private; the syncthreads in each segment's first
        // tile orders these stores before any lane's broadcast loads.

        // ======== layer 0 ========
        {
            int gc = 4 * tx;
            #pragma unroll
            for (int p = 0; p < 2; ++p) {
                unsigned long long br  = pack2(sBc0[gc + 2*p],       sBc0[gc + 2*p + 1]);
                unsigned long long bz  = pack2(sBc0[128 + gc + 2*p], sBc0[128 + gc + 2*p + 1]);
                unsigned long long bxn = pack2(sBc0[256 + gc + 2*p], sBc0[256 + gc + 2*p + 1]);
                unsigned long long bhn = pack2(sBc0[384 + gc + 2*p], sBc0[384 + gc + 2*p + 1]);
                #pragma unroll
                for (int i = 0; i < 8; ++i) { aR[i][p] = br; aZ[i][p] = bz; aXN[i][p] = bxn; aHN[i][p] = bhn; }
            }
        }
        gemm_seg<GCH>(0,  64,  sA + 0,  sWb, sWa, pbuf, tid, tx, ty, aR, aZ, aXN);
        gemm_seg<HID>(64, 192, sA + 64, sWb, sWa, pbuf, tid, tx, ty, aR, aZ, aHN);
        #pragma unroll
        for (int i = 0; i < 8; ++i) {
            int v = ty * 8 + i;
            float4 hp = *(const float4*)(sA + v * STR + 64 + 4 * tx);
            float rr[4], zz[4], xn[4], hn[4];
            unpack2(aR[i][0],  rr[0], rr[1]); unpack2(aR[i][1],  rr[2], rr[3]);
            unpack2(aZ[i][0],  zz[0], zz[1]); unpack2(aZ[i][1],  zz[2], zz[3]);
            unpack2(aXN[i][0], xn[0], xn[1]); unpack2(aXN[i][1], xn[2], xn[3]);
            unpack2(aHN[i][0], hn[0], hn[1]); unpack2(aHN[i][1], hn[2], hn[3]);
            float hv[4] = {hp.x, hp.y, hp.z, hp.w};
            #pragma unroll
            for (int j = 0; j < 4; ++j) {
                float r = fsig(rr[j]);
                float z = fsig(zz[j]);
                float n = ftanh_(fmaf(r, hn[j], xn[j]));
                hv[j] = (1.f - z) * n + z * hv[j];
            }
            // h1 rows warp-private: no barrier around this write
            *(float4*)(sA + v * STR + 64 + 4 * tx) = make_float4(hv[0], hv[1], hv[2], hv[3]);
        }

        // ======== layer 1 ========
        {
            int gc = 4 * tx;
            #pragma unroll
            for (int p = 0; p < 2; ++p) {
                unsigned long long br  = pack2(sBc1[gc + 2*p],       sBc1[gc + 2*p + 1]);
                unsigned long long bz  = pack2(sBc1[128 + gc + 2*p], sBc1[128 + gc + 2*p + 1]);
                unsigned long long bxn = pack2(sBc1[256 + gc + 2*p], sBc1[256 + gc + 2*p + 1]);
                unsigned long long bhn = pack2(sBc1[384 + gc + 2*p], sBc1[384 + gc + 2*p + 1]);
                #pragma unroll
                for (int i = 0; i < 8; ++i) { aR[i][p] = br; aZ[i][p] = bz; aXN[i][p] = bxn; aHN[i][p] = bhn; }
            }
        }
        gemm_seg<HID>(192, 320, sA + 64,  sWb, sWa, pbuf, tid, tx, ty, aR, aZ, aXN);
        gemm_seg<HID>(320, 0,   sA + 192, sWb, sWa, pbuf, tid, tx, ty, aR, aZ, aHN); // chain wraps to next step
        #pragma unroll
        for (int i = 0; i < 8; ++i) {
            int v = ty * 8 + i;
            float4 hp = *(const float4*)(sA + v * STR + 192 + 4 * tx);
            float rr[4], zz[4], xn[4], hn[4];
            unpack2(aR[i][0],  rr[0], rr[1]); unpack2(aR[i][1],  rr[2], rr[3]);
            unpack2(aZ[i][0],  zz[0], zz[1]); unpack2(aZ[i][1],  zz[2], zz[3]);
            unpack2(aXN[i][0], xn[0], xn[1]); unpack2(aXN[i][1], xn[2], xn[3]);
            unpack2(aHN[i][0], hn[0], hn[1]); unpack2(aHN[i][1], hn[2], hn[3]);
            float hv[4] = {hp.x, hp.y, hp.z, hp.w};
            #pragma unroll
            for (int j = 0; j < 4; ++j) {
                float r = fsig(rr[j]);
                float z = fsig(zz[j]);
                float n = ftanh_(fmaf(r, hn[j], xn[j]));
                hv[j] = (1.f - z) * n + z * hv[j];
            }
            float4 h4 = make_float4(hv[0], hv[1], hv[2], hv[3]);
            *(float4*)(sA + v * STR + 192 + 4 * tx) = h4;   // warp-private
            if (t == sLen[v] - 1)
                *(float4*)(out + (size_t)sVox[v] * (GCH + HID) + GCH + 4 * tx) = h4;
        }
    }

    // drain the chained cp group (no outstanding async copies at exit)
    asm volatile("cp.async.wait_group 0;\n" ::: "memory");

    // ---- tail: conv+max only for t in [tmax, 32); thread-owned, barrier-free ----
    for (int t = tmax; t < PPTS; ++t) {
        const float2* ip = (const float2*)(inputs + (inbase + t) * CIN);
        float2 i0 = ip[0], i1 = ip[1], i2 = ip[2], i3 = ip[3], i4 = ip[4];
        float in[10] = { i0.x, i0.y, i1.x, i1.y, i2.x, i2.y, i3.x, i3.y, i4.x, i4.y };
        #pragma unroll
        for (int q = 0; q < 4; ++q) {
            float4 m4 = *(float4*)(sMax + cv * GCH + cg + q * 4);
            float xv[4];
            #pragma unroll
            for (int c4 = 0; c4 < 4; ++c4) {
                int g = cg + q * 4 + c4;
                float s = sCb[g];
                const float* pw = sCw + g * CIN;
                #pragma unroll
                for (int c = 0; c < CIN; ++c) s = fmaf(in[c], pw[c], s);
                xv[c4] = fmaxf(s, 0.f);
            }
            m4.x = fmaxf(m4.x, xv[0]); m4.y = fmaxf(m4.y, xv[1]);
            m4.z = fmaxf(m4.z, xv[2]); m4.w = fmaxf(m4.w, xv[3]);
            *(float4*)(sMax + cv * GCH + cg + q * 4) = m4;
        }
    }

    // max-features output (thread owns voxel cv, cols cg..cg+15; reads own writes)
    {
        float* po = out + (size_t)sVox[cv] * (GCH + HID) + cg;
        #pragma unroll
        for (int q = 0; q < 4; ++q)
            *(float4*)(po + q * 4) = *(float4*)(sMax + cv * GCH + cg + q * 4);
    }
}

extern "C" void kernel_launch(void* const* d_in, const int* in_sizes, int n_in,
                              void* d_out, int out_size) {
    const float* inputs = (const float*)d_in[0];
    const int*   vnp    = (const int*)  d_in[1];
    // d_in[2] = mask (unused)
    const float* conv_w = (const float*)d_in[3];
    const float* bn_g   = (const float*)d_in[4];
    const float* bn_b   = (const float*)d_in[5];
    const float* bn_m   = (const float*)d_in[6];
    const float* bn_v   = (const float*)d_in[7];
    const float* wih0   = (const float*)d_in[8];
    const float* whh0   = (const float*)d_in[9];
    const float* bih0   = (const float*)d_in[10];
    const float* bhh0   = (const float*)d_in[11];
    const float* wih1   = (const float*)d_in[12];
    const float* whh1   = (const float*)d_in[13];
    const float* bih1   = (const float*)d_in[14];
    const float* bhh1   = (const float*)d_in[15];
    float* out = (float*)d_out;

    const int smem_bytes = (2 * KT * H3 + MB * STR + MB * GCH + GCH * CIN + GCH + 1024)
                           * (int)sizeof(float) + 2 * MB * (int)sizeof(int);
    cudaFuncSetAttribute(pfn_kernel, cudaFuncAttributeMaxDynamicSharedMemorySize, smem_bytes);

    zero_hist<<<1, 32>>>();
    hist_kernel<<<160, 256>>>(vnp);
    scan_kernel<<<1, 32>>>();
    sortblocks<<<(NVOX + 255) / 256, 256>>>(vnp);
    prep_weights<<<336, 512>>>(wih0, whh0, wih1, whh1);
    pfn_kernel<<<NBLOCKS, NTH, smem_bytes>>>(inputs, vnp, conv_w, bn_g, bn_b, bn_m, bn_v,
                                             bih0, bhh0, bih1, bhh1, out);
}

// round 9
// speedup vs baseline: 1.0294x; 1.0004x over previous
#include <cuda_runtime.h>
#include <math.h>
#include <stdint.h>

// Shapes (fixed)
#define NVOX 40000
#define PPTS 32
#define CIN  10
#define GCH  64
#define HID  128
#define H3   384
#define MB   64
#define NTH  256
#define NBLOCKS (NVOX / MB)     // 625
#define KT   32                 // K rows per weight tile
#define STR  320                // sA row: [x(64) | h1(128) | h2(128)]

// Stacked transposed weights WT[k][gate_col]:
// rows [0,64) Wih0^T, [64,192) Whh0^T, [192,320) Wih1^T, [320,448) Whh1^T
#define WT_ROWS 448
__device__ float g_WT[WT_ROWS * H3];
__device__ int   g_perm[NVOX];
__device__ int   g_hist[32];
__device__ int   g_off[33];
__device__ int   g_cursor[32];

__global__ void prep_weights(const float* __restrict__ wih0, const float* __restrict__ whh0,
                             const float* __restrict__ wih1, const float* __restrict__ whh1) {
    int idx = blockIdx.x * blockDim.x + threadIdx.x;
    const int total = WT_ROWS * H3;
    for (; idx < total; idx += gridDim.x * blockDim.x) {
        int row = idx / H3;
        int j   = idx - row * H3;
        float v;
        if (row < 64)       v = wih0[j * 64  + row];
        else if (row < 192) v = whh0[j * 128 + (row - 64)];
        else if (row < 320) v = wih1[j * 128 + (row - 192)];
        else                v = whh1[j * 128 + (row - 320)];
        g_WT[idx] = v;
    }
}

// ---- length binning (order within a bin unimportant: per-voxel outputs independent) ----
__global__ void zero_hist() {
    if (threadIdx.x < 32) { g_hist[threadIdx.x] = 0; g_cursor[threadIdx.x] = 0; }
}
__global__ void hist_kernel(const int* __restrict__ vnp) {
    int i = blockIdx.x * blockDim.x + threadIdx.x;
    for (; i < NVOX; i += gridDim.x * blockDim.x)
        atomicAdd(&g_hist[vnp[i] - 1], 1);
}
__global__ void scan_kernel() {
    if (threadIdx.x == 0) {
        int acc = 0; g_off[0] = 0;
        for (int b = 0; b < 32; ++b) { acc += g_hist[b]; g_off[b + 1] = acc; }
    }
}
__global__ void sortblocks(const int* __restrict__ vnp) {
    __shared__ int cnt[32];
    __shared__ int sbase[32];
    const int tid = threadIdx.x;
    if (tid < 32) cnt[tid] = 0;
    __syncthreads();
    int i = blockIdx.x * 256 + tid;
    int len = -1, myrank = 0;
    if (i < NVOX) { len = vnp[i] - 1; myrank = atomicAdd(&cnt[len], 1); }
    __syncthreads();
    if (tid < 32 && cnt[tid] > 0) sbase[tid] = atomicAdd(&g_cursor[tid], cnt[tid]);
    __syncthreads();
    if (i < NVOX) g_perm[g_off[len] + sbase[len] + myrank] = i;
}

// ---- f32x2 helpers ----
__device__ __forceinline__ unsigned long long pack2(float lo, float hi) {
    unsigned long long r;
    asm("mov.b64 %0, {%1, %2};" : "=l"(r) : "f"(lo), "f"(hi));
    return r;
}
__device__ __forceinline__ void unpack2(unsigned long long v, float& lo, float& hi) {
    asm("mov.b64 {%0, %1}, %2;" : "=f"(lo), "=f"(hi) : "l"(v));
}
__device__ __forceinline__ void ffma2(unsigned long long& d, unsigned long long a, unsigned long long b) {
    asm("fma.rn.f32x2 %0, %1, %2, %0;" : "+l"(d) : "l"(a), "l"(b));
}
// Fast gates via MUFU paths (~2 ulp): saturate correctly at both tails.
__device__ __forceinline__ float fsig(float x)  { return __fdividef(1.f, 1.f + __expf(-x)); }
__device__ __forceinline__ float ftanh_(float x){ return 1.f - __fdividef(2.f, __expf(2.f * x) + 1.f); }

// cp.async one KT x 384 weight tile (49152 B = 3072 x 16B, 12 per thread at 256 thr)
__device__ __forceinline__ void cp_tile(uint32_t dst_s, const float* __restrict__ src, int tid) {
    const char* s = (const char*)src;
    #pragma unroll
    for (int r = 0; r < 12; ++r) {
        int idx = tid + r * NTH;
        asm volatile("cp.async.cg.shared.global [%0], [%1], 16;\n"
                     :: "r"(dst_s + idx * 16), "l"(s + (size_t)idx * 16) : "memory");
    }
    asm volatile("cp.async.commit_group;\n" ::: "memory");
}

// One KT-tile GEMM: thread (tx,ty) -> voxels ty*8..ty*8+7, per-gate cols 4tx..4tx+3.
// Software-pipelined: weight row kk+1 prefetched during kk's FFMA2 block.
// (kk=31 prefetch over-reads one row into the adjacent smem region: allocated, unused.)
__device__ __forceinline__ void tile_compute(
    const float* __restrict__ buf, const float* __restrict__ sA0, int tx, int ty,
    unsigned long long (&aR)[8][2], unsigned long long (&aZ)[8][2], unsigned long long (&aN)[8][2])
{
    const float* wcol = buf + 4 * tx;
    ulonglong2 wr = *(const ulonglong2*)(wcol);
    ulonglong2 wz = *(const ulonglong2*)(wcol + HID);
    ulonglong2 wn = *(const ulonglong2*)(wcol + 2 * HID);
    #pragma unroll 2
    for (int kk4 = 0; kk4 < KT / 4; ++kk4) {
        float4 a4[8];
        #pragma unroll
        for (int i = 0; i < 8; ++i)
            a4[i] = *(const float4*)(sA0 + (ty * 8 + i) * STR + kk4 * 4);
        #pragma unroll
        for (int j = 0; j < 4; ++j) {
            const float* nrow = wcol + (kk4 * 4 + j + 1) * H3;
            ulonglong2 nr = *(const ulonglong2*)(nrow);
            ulonglong2 nz = *(const ulonglong2*)(nrow + HID);
            ulonglong2 nn = *(const ulonglong2*)(nrow + 2 * HID);
            #pragma unroll
            for (int i = 0; i < 8; ++i) {
                float a = (j == 0) ? a4[i].x : (j == 1) ? a4[i].y
                        : (j == 2) ? a4[i].z : a4[i].w;
                unsigned long long a2 = pack2(a, a);
                ffma2(aR[i][0], a2, wr.x); ffma2(aR[i][1], a2, wr.y);
                ffma2(aZ[i][0], a2, wz.x); ffma2(aZ[i][1], a2, wz.y);
                ffma2(aN[i][0], a2, wn.x); ffma2(aN[i][1], a2, wn.y);
            }
            wr = nr; wz = nz; wn = nn;
        }
    }
}

// Chained double-buffered GEMM segment over WT rows [rowBase, rowBase+SEGK).
// On entry: one cp group outstanding, targeting buffer pbuf, holding row rowBase.
// Each tile waits, syncs, issues the next row in the global chain (wrapping into
// nextRowAfter at segment end), computes, flips pbuf.
template<int SEGK>
__device__ __forceinline__ void gemm_seg(
    int rowBase, int nextRowAfter, const float* __restrict__ sA0,
    const float* const sWb[2], const uint32_t sWa[2], int& pbuf,
    int tid, int tx, int ty,
    unsigned long long (&aR)[8][2], unsigned long long (&aZ)[8][2], unsigned long long (&aN)[8][2])
{
    const int NT = SEGK / KT;
    #pragma unroll 1
    for (int tile = 0; tile < NT; ++tile) {
        asm volatile("cp.async.wait_group 0;\n" ::: "memory");
        __syncthreads();
        int nrow = (tile + 1 < NT) ? rowBase + (tile + 1) * KT : nextRowAfter;
        cp_tile(sWa[pbuf ^ 1], g_WT + (size_t)nrow * H3, tid);
        tile_compute(sWb[pbuf], sA0 + tile * KT, tx, ty, aR, aZ, aN);
        pbuf ^= 1;
    }
}

__global__ void __launch_bounds__(NTH)
pfn_kernel(const float* __restrict__ inputs, const int* __restrict__ vnp,
           const float* __restrict__ conv_w,
           const float* __restrict__ bn_gamma, const float* __restrict__ bn_beta,
           const float* __restrict__ bn_mean,  const float* __restrict__ bn_var,
           const float* __restrict__ b_ih0, const float* __restrict__ b_hh0,
           const float* __restrict__ b_ih1, const float* __restrict__ b_hh1,
           float* __restrict__ out)
{
    extern __shared__ float sm[];
    float* sW0  = sm;                     // 12288
    float* sW1  = sW0 + KT * H3;          // 12288
    float* sA   = sW1 + KT * H3;          // 64*320
    float* sMax = sA  + MB * STR;         // 64*64
    float* sCw  = sMax + MB * GCH;        // 640
    float* sCb  = sCw + GCH * CIN;        // 64
    // combined bias per layer: [0,128)=bir+bhr [128,256)=biz+bhz [256,384)=bin [384,512)=bhn
    float* sBc0 = sCb  + GCH;             // 512
    float* sBc1 = sBc0 + 512;             // 512
    int*   sLen = (int*)(sBc1 + 512);     // 64
    int*   sVox = sLen + MB;              // 64

    const int tid = threadIdx.x;
    const int tx = tid & 31, ty = tid >> 5;        // warp ty owns voxels ty*8..ty*8+7
    const int cv = tid >> 2, cg = (tid & 3) * 16;  // conv: 1 voxel, 16 cols (same warp as GEMM owner)
    const int pbase = (NBLOCKS - 1 - (int)blockIdx.x) * MB;   // LPT: longest first

    const float* sWb[2] = { sW0, sW1 };
    uint32_t sWa[2] = { (uint32_t)__cvta_generic_to_shared(sW0),
                        (uint32_t)__cvta_generic_to_shared(sW1) };

    // ---- one-time setup ----
    for (int idx = tid; idx < MB * STR; idx += NTH) sA[idx] = 0.f;
    for (int idx = tid; idx < MB * GCH; idx += NTH) sMax[idx] = 0.f;
    for (int idx = tid; idx < GCH * CIN; idx += NTH) {
        int g = idx / CIN;
        float sc = bn_gamma[g] * rsqrtf(bn_var[g] + 1e-5f);
        sCw[idx] = conv_w[idx] * sc;
    }
    for (int idx = tid; idx < GCH; idx += NTH) {
        float sc = bn_gamma[idx] * rsqrtf(bn_var[idx] + 1e-5f);
        sCb[idx] = bn_beta[idx] - bn_mean[idx] * sc;
    }
    for (int idx = tid; idx < 512; idx += NTH) {
        float v0, v1;
        if (idx < 256)      { v0 = b_ih0[idx] + b_hh0[idx]; v1 = b_ih1[idx] + b_hh1[idx]; }
        else if (idx < 384) { v0 = b_ih0[idx]; v1 = b_ih1[idx]; }             // xn bias
        else                { v0 = b_hh0[idx - 128]; v1 = b_hh1[idx - 128]; } // hn bias
        sBc0[idx] = v0; sBc1[idx] = v1;
    }
    for (int idx = tid; idx < MB; idx += NTH) {
        int vox = g_perm[pbase + idx];
        sVox[idx] = vox;
        sLen[idx] = vnp[vox];
    }
    __syncthreads();

    int tmax = 0;
    for (int v = 0; v < MB; ++v) tmax = max(tmax, sLen[v]);
    const size_t inbase = (size_t)sVox[cv] * PPTS;

    unsigned long long aR[8][2], aZ[8][2], aXN[8][2], aHN[8][2];
    int pbuf = 0;
    cp_tile(sWa[0], g_WT, tid);   // prime the chain with row 0

    for (int t = 0; t < tmax; ++t) {
        // ---- conv+BN+ReLU (warp-private: cv in this warp's voxel set; 16 cols/thread) ----
        {
            const float2* ip = (const float2*)(inputs + (inbase + t) * CIN);
            float2 i0 = ip[0], i1 = ip[1], i2 = ip[2], i3 = ip[3], i4 = ip[4];
            float in[10] = { i0.x, i0.y, i1.x, i1.y, i2.x, i2.y, i3.x, i3.y, i4.x, i4.y };
            #pragma unroll
            for (int q = 0; q < 4; ++q) {
                float xv[4];
                #pragma unroll
                for (int c4 = 0; c4 < 4; ++c4) {
                    int g = cg + q * 4 + c4;
                    float s = sCb[g];
                    const float* pw = sCw + g * CIN;
                    #pragma unroll
                    for (int c = 0; c < CIN; ++c) s = fmaf(in[c], pw[c], s);
                    xv[c4] = fmaxf(s, 0.f);
                }
                float4 x4 = make_float4(xv[0], xv[1], xv[2], xv[3]);
                *(float4*)(sA + cv * STR + cg + q * 4) = x4;
                float4 m4 = *(float4*)(sMax + cv * GCH + cg + q * 4);   // same-thread RMW: no race
                m4.x = fmaxf(m4.x, x4.x); m4.y = fmaxf(m4.y, x4.y);
                m4.z = fmaxf(m4.z, x4.z); m4.w = fmaxf(m4.w, x4.w);
                *(float4*)(sMax + cv * GCH + cg + q * 4) = m4;
            }
        }
        // x / h1 / h2 rows are warp-private; the syncthreads in each segment's first
        // tile orders these stores before any lane's broadcast loads.

        // ======== layer 0 ========
        {
            int gc = 4 * tx;
            #pragma unroll
            for (int p = 0; p < 2; ++p) {
                unsigned long long br  = pack2(sBc0[gc + 2*p],       sBc0[gc + 2*p + 1]);
                unsigned long long bz  = pack2(sBc0[128 + gc + 2*p], sBc0[128 + gc + 2*p + 1]);
                unsigned long long bxn = pack2(sBc0[256 + gc + 2*p], sBc0[256 + gc + 2*p + 1]);
                unsigned long long bhn = pack2(sBc0[384 + gc + 2*p], sBc0[384 + gc + 2*p + 1]);
                #pragma unroll
                for (int i = 0; i < 8; ++i) { aR[i][p] = br; aZ[i][p] = bz; aXN[i][p] = bxn; aHN[i][p] = bhn; }
            }
        }
        gemm_seg<GCH>(0,  64,  sA + 0,  sWb, sWa, pbuf, tid, tx, ty, aR, aZ, aXN);
        gemm_seg<HID>(64, 192, sA + 64, sWb, sWa, pbuf, tid, tx, ty, aR, aZ, aHN);
        #pragma unroll
        for (int i = 0; i < 8; ++i) {
            int v = ty * 8 + i;
            float4 hp = *(const float4*)(sA + v * STR + 64 + 4 * tx);
            float rr[4], zz[4], xn[4], hn[4];
            unpack2(aR[i][0],  rr[0], rr[1]); unpack2(aR[i][1],  rr[2], rr[3]);
            unpack2(aZ[i][0],  zz[0], zz[1]); unpack2(aZ[i][1],  zz[2], zz[3]);
            unpack2(aXN[i][0], xn[0], xn[1]); unpack2(aXN[i][1], xn[2], xn[3]);
            unpack2(aHN[i][0], hn[0], hn[1]); unpack2(aHN[i][1], hn[2], hn[3]);
            float hv[4] = {hp.x, hp.y, hp.z, hp.w};
            #pragma unroll
            for (int j = 0; j < 4; ++j) {
                float r = fsig(rr[j]);
                float z = fsig(zz[j]);
                float n = ftanh_(fmaf(r, hn[j], xn[j]));
                hv[j] = (1.f - z) * n + z * hv[j];
            }
            // h1 rows warp-private: no barrier around this write
            *(float4*)(sA + v * STR + 64 + 4 * tx) = make_float4(hv[0], hv[1], hv[2], hv[3]);
        }

        // ======== layer 1 ========
        {
            int gc = 4 * tx;
            #pragma unroll
            for (int p = 0; p < 2; ++p) {
                unsigned long long br  = pack2(sBc1[gc + 2*p],       sBc1[gc + 2*p + 1]);
                unsigned long long bz  = pack2(sBc1[128 + gc + 2*p], sBc1[128 + gc + 2*p + 1]);
                unsigned long long bxn = pack2(sBc1[256 + gc + 2*p], sBc1[256 + gc + 2*p + 1]);
                unsigned long long bhn = pack2(sBc1[384 + gc + 2*p], sBc1[384 + gc + 2*p + 1]);
                #pragma unroll
                for (int i = 0; i < 8; ++i) { aR[i][p] = br; aZ[i][p] = bz; aXN[i][p] = bxn; aHN[i][p] = bhn; }
            }
        }
        gemm_seg<HID>(192, 320, sA + 64,  sWb, sWa, pbuf, tid, tx, ty, aR, aZ, aXN);
        gemm_seg<HID>(320, 0,   sA + 192, sWb, sWa, pbuf, tid, tx, ty, aR, aZ, aHN); // chain wraps to next step
        #pragma unroll
        for (int i = 0; i < 8; ++i) {
            int v = ty * 8 + i;
            float4 hp = *(const float4*)(sA + v * STR + 192 + 4 * tx);
            float rr[4], zz[4], xn[4], hn[4];
            unpack2(aR[i][0],  rr[0], rr[1]); unpack2(aR[i][1],  rr[2], rr[3]);
            unpack2(aZ[i][0],  zz[0], zz[1]); unpack2(aZ[i][1],  zz[2], zz[3]);
            unpack2(aXN[i][0], xn[0], xn[1]); unpack2(aXN[i][1], xn[2], xn[3]);
            unpack2(aHN[i][0], hn[0], hn[1]); unpack2(aHN[i][1], hn[2], hn[3]);
            float hv[4] = {hp.x, hp.y, hp.z, hp.w};
            #pragma unroll
            for (int j = 0; j < 4; ++j) {
                float r = fsig(rr[j]);
                float z = fsig(zz[j]);
                float n = ftanh_(fmaf(r, hn[j], xn[j]));
                hv[j] = (1.f - z) * n + z * hv[j];
            }
            float4 h4 = make_float4(hv[0], hv[1], hv[2], hv[3]);
            *(float4*)(sA + v * STR + 192 + 4 * tx) = h4;   // warp-private
            if (t == sLen[v] - 1)
                *(float4*)(out + (size_t)sVox[v] * (GCH + HID) + GCH + 4 * tx) = h4;
        }
    }

    // drain the chained cp group (no outstanding async copies at exit)
    asm volatile("cp.async.wait_group 0;\n" ::: "memory");

    // ---- tail: conv+max only for t in [tmax, 32); thread-owned, barrier-free ----
    for (int t = tmax; t < PPTS; ++t) {
        const float2* ip = (const float2*)(inputs + (inbase + t) * CIN);
        float2 i0 = ip[0], i1 = ip[1], i2 = ip[2], i3 = ip[3], i4 = ip[4];
        float in[10] = { i0.x, i0.y, i1.x, i1.y, i2.x, i2.y, i3.x, i3.y, i4.x, i4.y };
        #pragma unroll
        for (int q = 0; q < 4; ++q) {
            float4 m4 = *(float4*)(sMax + cv * GCH + cg + q * 4);
            float xv[4];
            #pragma unroll
            for (int c4 = 0; c4 < 4; ++c4) {
                int g = cg + q * 4 + c4;
                float s = sCb[g];
                const float* pw = sCw + g * CIN;
                #pragma unroll
                for (int c = 0; c < CIN; ++c) s = fmaf(in[c], pw[c], s);
                xv[c4] = fmaxf(s, 0.f);
            }
            m4.x = fmaxf(m4.x, xv[0]); m4.y = fmaxf(m4.y, xv[1]);
            m4.z = fmaxf(m4.z, xv[2]); m4.w = fmaxf(m4.w, xv[3]);
            *(float4*)(sMax + cv * GCH + cg + q * 4) = m4;
        }
    }

    // max-features output (thread owns voxel cv, cols cg..cg+15; reads own writes)
    {
        float* po = out + (size_t)sVox[cv] * (GCH + HID) + cg;
        #pragma unroll
        for (int q = 0; q < 4; ++q)
            *(float4*)(po + q * 4) = *(float4*)(sMax + cv * GCH + cg + q * 4);
    }
}

extern "C" void kernel_launch(void* const* d_in, const int* in_sizes, int n_in,
                              void* d_out, int out_size) {
    const float* inputs = (const float*)d_in[0];
    const int*   vnp    = (const int*)  d_in[1];
    // d_in[2] = mask (unused)
    const float* conv_w = (const float*)d_in[3];
    const float* bn_g   = (const float*)d_in[4];
    const float* bn_b   = (const float*)d_in[5];
    const float* bn_m   = (const float*)d_in[6];
    const float* bn_v   = (const float*)d_in[7];
    const float* wih0   = (const float*)d_in[8];
    const float* whh0   = (const float*)d_in[9];
    const float* bih0   = (const float*)d_in[10];
    const float* bhh0   = (const float*)d_in[11];
    const float* wih1   = (const float*)d_in[12];
    const float* whh1   = (const float*)d_in[13];
    const float* bih1   = (const float*)d_in[14];
    const float* bhh1   = (const float*)d_in[15];
    float* out = (float*)d_out;

    const int smem_bytes = (2 * KT * H3 + MB * STR + MB * GCH + GCH * CIN + GCH + 1024)
                           * (int)sizeof(float) + 2 * MB * (int)sizeof(int);
    cudaFuncSetAttribute(pfn_kernel, cudaFuncAttributeMaxDynamicSharedMemorySize, smem_bytes);

    zero_hist<<<1, 32>>>();
    hist_kernel<<<160, 256>>>(vnp);
    scan_kernel<<<1, 32>>>();
    sortblocks<<<(NVOX + 255) / 256, 256>>>(vnp);
    prep_weights<<<336, 512>>>(wih0, whh0, wih1, whh1);
    pfn_kernel<<<NBLOCKS, NTH, smem_bytes>>>(inputs, vnp, conv_w, bn_g, bn_b, bn_m, bn_v,
                                             bih0, bhh0, bih1, bhh1, out);
}